// round 5
// baseline (speedup 1.0000x reference)
#include <cuda_runtime.h>
#include <math.h>

#define N_ATOMS 40000
#define N_BONDS 90000
#define MAX_NB 6
#define ATOM_FDIM 133
#define BOND_FDIM 147
#define HID 300
#define DEPTH 6
#define CAT_DIM (ATOM_FDIM + HID)   // 433

#define H4   (HID / 4)              // 75
#define H34  (3 * HID / 4)          // 225

// ---------------- scratch (device globals; no cudaMalloc allowed) -------------
__device__ float g_inp [N_BONDS * HID];
__device__ float g_gi  [N_BONDS * 3 * HID];
__device__ float g_msg [N_BONDS * HID];
__device__ float g_h   [N_BONDS * HID];
__device__ float g_amsg[N_ATOMS * HID];
__device__ float g_ain [N_ATOMS * CAT_DIM];

// ================= common MMA helpers ==========================================
__device__ __forceinline__ unsigned smem_u32(const void* p) {
    return (unsigned)__cvta_generic_to_shared(p);
}
__device__ __forceinline__ void cp16(unsigned dst, const void* src) {
    asm volatile("cp.async.cg.shared.global [%0], [%1], 16;\n" :: "r"(dst), "l"(src));
}
__device__ __forceinline__ void cp4(unsigned dst, const void* src) {
    asm volatile("cp.async.ca.shared.global [%0], [%1], 4;\n" :: "r"(dst), "l"(src));
}
__device__ __forceinline__ void cp_commit() { asm volatile("cp.async.commit_group;\n"); }
__device__ __forceinline__ void cp_wait0()  { asm volatile("cp.async.wait_group 0;\n"); }
__device__ __forceinline__ void sts_zero16(unsigned dst) {
    asm volatile("st.shared.v4.b32 [%0], {%1,%1,%1,%1};" :: "r"(dst), "r"(0));
}
__device__ __forceinline__ void sts_zero4(unsigned dst) {
    asm volatile("st.shared.b32 [%0], %1;" :: "r"(dst), "r"(0));
}
__device__ __forceinline__ void mma_tf32(float* c, const unsigned* a, const unsigned* b) {
    asm volatile(
        "mma.sync.aligned.m16n8k8.row.col.f32.tf32.tf32.f32 "
        "{%0,%1,%2,%3},{%4,%5,%6,%7},{%8,%9},{%0,%1,%2,%3};"
        : "+f"(c[0]), "+f"(c[1]), "+f"(c[2]), "+f"(c[3])
        : "r"(a[0]), "r"(a[1]), "r"(a[2]), "r"(a[3]), "r"(b[0]), "r"(b[1]));
}
__device__ __forceinline__ void tf32_split(float v, unsigned& hi, unsigned& lo) {
    asm("cvt.rna.tf32.f32 %0, %1;" : "=r"(hi) : "f"(v));
    float l = v - __uint_as_float(hi);
    asm("cvt.rna.tf32.f32 %0, %1;" : "=r"(lo) : "f"(l));
}
__device__ __forceinline__ float sigmoidf1(float x) { return 1.f / (1.f + expf(-x)); }

// ================= generic 3xTF32 TN GEMM (round-3 proven) =====================
#define BM 128
#define BN 128
#define BK 16
#define SPAD 20

__global__ void __launch_bounds__(256)
mma_gemm_tn(const float* __restrict__ A, const float* __restrict__ B,
            const float* __restrict__ bias, const float* __restrict__ mask,
            float* __restrict__ C, int M, int N, int K, int relu)
{
    __shared__ float As[2][BM][SPAD];
    __shared__ float Bs[2][BN][SPAD];

    const int tid  = threadIdx.x;
    const int wid  = tid >> 5;
    const int lane = tid & 31;
    const int g = lane >> 2, t = lane & 3;
    const int warp_m = wid & 1;
    const int warp_n = wid >> 1;
    const int m0 = blockIdx.y * BM;
    const int n0 = blockIdx.x * BN;
    const int KT = (K + BK - 1) / BK;
    const bool vec = ((K & 3) == 0);

    float acc[4][4][4];
    #pragma unroll
    for (int mi = 0; mi < 4; mi++)
        #pragma unroll
        for (int ni = 0; ni < 4; ni++)
            #pragma unroll
            for (int r = 0; r < 4; r++) acc[mi][ni][r] = 0.f;

    auto load_tile = [&](int kt, int s) {
        const int k0 = kt * BK;
        unsigned abase = smem_u32(&As[s][0][0]);
        unsigned bbase = smem_u32(&Bs[s][0][0]);
        if (vec) {
            #pragma unroll
            for (int i = 0; i < 2; i++) {
                int idx = tid + i * 256;
                int row = idx >> 2;
                int seg = idx & 3;
                int gk  = k0 + seg * 4;
                unsigned da = abase + (unsigned)(row * SPAD + seg * 4) * 4u;
                unsigned db = bbase + (unsigned)(row * SPAD + seg * 4) * 4u;
                int gm = m0 + row, gn = n0 + row;
                if (gm < M && gk < K) cp16(da, A + (size_t)gm * K + gk);
                else                  sts_zero16(da);
                if (gn < N && gk < K) cp16(db, B + (size_t)gn * K + gk);
                else                  sts_zero16(db);
            }
        } else {
            #pragma unroll
            for (int i = 0; i < 8; i++) {
                int idx = tid + i * 256;
                int row = idx >> 4;
                int kk  = idx & 15;
                int gk  = k0 + kk;
                unsigned da = abase + (unsigned)(row * SPAD + kk) * 4u;
                unsigned db = bbase + (unsigned)(row * SPAD + kk) * 4u;
                int gm = m0 + row, gn = n0 + row;
                if (gm < M && gk < K) cp4(da, A + (size_t)gm * K + gk);
                else                  sts_zero4(da);
                if (gn < N && gk < K) cp4(db, B + (size_t)gn * K + gk);
                else                  sts_zero4(db);
            }
        }
    };

    load_tile(0, 0);
    cp_commit();

    for (int kt = 0; kt < KT; kt++) {
        cp_wait0();
        __syncthreads();
        const int cur = kt & 1;
        if (kt + 1 < KT) load_tile(kt + 1, cur ^ 1);
        cp_commit();

        #pragma unroll
        for (int kk = 0; kk < BK; kk += 8) {
            unsigned ah[4][4], al[4][4], bh[4][2], bl[4][2];
            #pragma unroll
            for (int mi = 0; mi < 4; mi++) {
                int m = warp_m * 64 + mi * 16;
                tf32_split(As[cur][m + g     ][kk + t    ], ah[mi][0], al[mi][0]);
                tf32_split(As[cur][m + g + 8 ][kk + t    ], ah[mi][1], al[mi][1]);
                tf32_split(As[cur][m + g     ][kk + t + 4], ah[mi][2], al[mi][2]);
                tf32_split(As[cur][m + g + 8 ][kk + t + 4], ah[mi][3], al[mi][3]);
            }
            #pragma unroll
            for (int ni = 0; ni < 4; ni++) {
                int n = warp_n * 32 + ni * 8;
                tf32_split(Bs[cur][n + g][kk + t    ], bh[ni][0], bl[ni][0]);
                tf32_split(Bs[cur][n + g][kk + t + 4], bh[ni][1], bl[ni][1]);
            }
            #pragma unroll
            for (int mi = 0; mi < 4; mi++)
                #pragma unroll
                for (int ni = 0; ni < 4; ni++) {
                    mma_tf32(acc[mi][ni], al[mi], bh[ni]);
                    mma_tf32(acc[mi][ni], ah[mi], bl[ni]);
                    mma_tf32(acc[mi][ni], ah[mi], bh[ni]);
                }
        }
    }

    #pragma unroll
    for (int mi = 0; mi < 4; mi++) {
        #pragma unroll
        for (int ni = 0; ni < 4; ni++) {
            int cn = n0 + warp_n * 32 + ni * 8 + 2 * t;
            float b0 = 0.f, b1 = 0.f;
            if (bias) {
                if (cn     < N) b0 = bias[cn];
                if (cn + 1 < N) b1 = bias[cn + 1];
            }
            #pragma unroll
            for (int half = 0; half < 2; half++) {
                int rm = m0 + warp_m * 64 + mi * 16 + g + half * 8;
                if (rm >= M) continue;
                float v0 = acc[mi][ni][half * 2 + 0] + b0;
                float v1 = acc[mi][ni][half * 2 + 1] + b1;
                if (relu) { v0 = fmaxf(v0, 0.f); v1 = fmaxf(v1, 0.f); }
                if (mask) { float mk = mask[rm]; v0 *= mk; v1 *= mk; }
                if (cn + 1 < N) {
                    float2 v = {v0, v1};
                    *(float2*)(C + (size_t)rm * N + cn) = v;
                } else if (cn < N) {
                    C[(size_t)rm * N + cn] = v0;
                }
            }
        }
    }
}

// ================= fused gh GEMM + GRU =========================================
// For 128 bond-rows x 64 hidden cols, accumulate all 3 gates:
//   gh_g[m,j] = sum_k h[m,k] * W_hh[g*300 + j, k]
// then epilogue: r,z,n gates + blend -> msg (row 0 zeroed).
#define FBM 128
#define FBN 64

__global__ void __launch_bounds__(256)
gh_gru_fused(const float* __restrict__ H, const float* __restrict__ Whh,
             const float* __restrict__ b_hh, const float* __restrict__ gi,
             float* __restrict__ msg)
{
    __shared__ float As[2][FBM][SPAD];          // h tile
    __shared__ float Bs[2][3][FBN][SPAD];       // 3 gate weight tiles

    const int tid  = threadIdx.x;
    const int wid  = tid >> 5;
    const int lane = tid & 31;
    const int g = lane >> 2, t = lane & 3;
    const int warp_m = wid & 3;     // 4 warps x 32 rows
    const int warp_n = wid >> 2;    // 2 warps x 32 cols
    const int m0 = blockIdx.y * FBM;
    const int n0 = blockIdx.x * FBN;
    const int K = HID;              // 300
    const int KT = (K + BK - 1) / BK;   // 19

    float acc[3][2][4][4];
    #pragma unroll
    for (int gt = 0; gt < 3; gt++)
        #pragma unroll
        for (int mi = 0; mi < 2; mi++)
            #pragma unroll
            for (int ni = 0; ni < 4; ni++)
                #pragma unroll
                for (int r = 0; r < 4; r++) acc[gt][mi][ni][r] = 0.f;

    auto load_tile = [&](int kt, int s) {
        const int k0 = kt * BK;
        unsigned abase = smem_u32(&As[s][0][0]);
        unsigned bbase = smem_u32(&Bs[s][0][0][0]);
        // A: 128 rows x 16 k = 512 float4
        #pragma unroll
        for (int i = 0; i < 2; i++) {
            int idx = tid + i * 256;
            int row = idx >> 2, seg = idx & 3;
            int gk = k0 + seg * 4;
            unsigned da = abase + (unsigned)(row * SPAD + seg * 4) * 4u;
            int gm = m0 + row;
            if (gm < N_BONDS && gk < K) cp16(da, H + (size_t)gm * K + gk);
            else                        sts_zero16(da);
        }
        // B: 3 gates x 64 rows x 16 k = 768 float4
        #pragma unroll
        for (int i = 0; i < 3; i++) {
            int idx = tid + i * 256;
            int brow = idx >> 2, seg = idx & 3;
            int gt = brow >> 6, n = brow & 63;
            int gk = k0 + seg * 4;
            unsigned db = bbase + (unsigned)(((gt * FBN + n) * SPAD) + seg * 4) * 4u;
            int wrow = n0 + n;
            if (wrow < HID && gk < K)
                cp16(db, Whh + (size_t)(gt * HID + wrow) * K + gk);
            else
                sts_zero16(db);
        }
    };

    load_tile(0, 0);
    cp_commit();

    for (int kt = 0; kt < KT; kt++) {
        cp_wait0();
        __syncthreads();
        const int cur = kt & 1;
        if (kt + 1 < KT) load_tile(kt + 1, cur ^ 1);
        cp_commit();

        #pragma unroll
        for (int kk = 0; kk < BK; kk += 8) {
            unsigned ah[2][4], al[2][4];
            #pragma unroll
            for (int mi = 0; mi < 2; mi++) {
                int m = warp_m * 32 + mi * 16;
                tf32_split(As[cur][m + g     ][kk + t    ], ah[mi][0], al[mi][0]);
                tf32_split(As[cur][m + g + 8 ][kk + t    ], ah[mi][1], al[mi][1]);
                tf32_split(As[cur][m + g     ][kk + t + 4], ah[mi][2], al[mi][2]);
                tf32_split(As[cur][m + g + 8 ][kk + t + 4], ah[mi][3], al[mi][3]);
            }
            #pragma unroll
            for (int gt = 0; gt < 3; gt++) {
                #pragma unroll
                for (int ni = 0; ni < 4; ni++) {
                    int n = warp_n * 32 + ni * 8;
                    unsigned bh[2], bl[2];
                    tf32_split(Bs[cur][gt][n + g][kk + t    ], bh[0], bl[0]);
                    tf32_split(Bs[cur][gt][n + g][kk + t + 4], bh[1], bl[1]);
                    #pragma unroll
                    for (int mi = 0; mi < 2; mi++) {
                        mma_tf32(acc[gt][mi][ni], al[mi], bh);
                        mma_tf32(acc[gt][mi][ni], ah[mi], bl);
                        mma_tf32(acc[gt][mi][ni], ah[mi], bh);
                    }
                }
            }
        }
    }

    // epilogue: GRU
    #pragma unroll
    for (int mi = 0; mi < 2; mi++) {
        #pragma unroll
        for (int ni = 0; ni < 4; ni++) {
            int cj = n0 + warp_n * 32 + ni * 8 + 2 * t;
            if (cj >= HID) continue;
            bool two = (cj + 1 < HID);
            float br0 = b_hh[cj],           br1 = two ? b_hh[cj + 1] : 0.f;
            float bz0 = b_hh[HID + cj],     bz1 = two ? b_hh[HID + cj + 1] : 0.f;
            float bn0 = b_hh[2 * HID + cj], bn1 = two ? b_hh[2 * HID + cj + 1] : 0.f;
            #pragma unroll
            for (int half = 0; half < 2; half++) {
                int rm = m0 + warp_m * 32 + mi * 16 + g + half * 8;
                if (rm >= N_BONDS) continue;
                if (rm == 0) {
                    if (two) *(float2*)(msg + (size_t)rm * HID + cj) = make_float2(0.f, 0.f);
                    else     msg[(size_t)rm * HID + cj] = 0.f;
                    continue;
                }
                size_t gib = (size_t)rm * 3 * HID;
                float hr0 = acc[0][mi][ni][half*2+0] + br0;
                float hz0 = acc[1][mi][ni][half*2+0] + bz0;
                float hn0 = acc[2][mi][ni][half*2+0] + bn0;
                float ir0 = gi[gib + cj];
                float iz0 = gi[gib + HID + cj];
                float in0 = gi[gib + 2 * HID + cj];
                float h0  = H[(size_t)rm * HID + cj];
                float r0 = sigmoidf1(ir0 + hr0);
                float z0 = sigmoidf1(iz0 + hz0);
                float nn0 = tanhf(in0 + r0 * hn0);
                float o0 = (1.f - z0) * nn0 + z0 * h0;
                if (two) {
                    float hr1 = acc[0][mi][ni][half*2+1] + br1;
                    float hz1 = acc[1][mi][ni][half*2+1] + bz1;
                    float hn1 = acc[2][mi][ni][half*2+1] + bn1;
                    float ir1 = gi[gib + cj + 1];
                    float iz1 = gi[gib + HID + cj + 1];
                    float in1 = gi[gib + 2 * HID + cj + 1];
                    float h1  = H[(size_t)rm * HID + cj + 1];
                    float r1 = sigmoidf1(ir1 + hr1);
                    float z1 = sigmoidf1(iz1 + hz1);
                    float nn1 = tanhf(in1 + r1 * hn1);
                    float o1 = (1.f - z1) * nn1 + z1 * h1;
                    *(float2*)(msg + (size_t)rm * HID + cj) = make_float2(o0, o1);
                } else {
                    msg[(size_t)rm * HID + cj] = o0;
                }
            }
        }
    }
}

// ================= elementwise (float4) =========================================
__global__ void gather_sum4(const float4* __restrict__ msg,
                            const int* __restrict__ a2b,
                            float4* __restrict__ amsg)
{
    int idx = blockIdx.x * blockDim.x + threadIdx.x;
    if (idx >= N_ATOMS * H4) return;
    int a = idx / H4;
    int j = idx - a * H4;
    const int* nb = a2b + (size_t)a * MAX_NB;
    float4 s = {0.f, 0.f, 0.f, 0.f};
    #pragma unroll
    for (int i = 0; i < MAX_NB; i++) {
        float4 v = msg[(size_t)nb[i] * H4 + j];
        s.x += v.x; s.y += v.y; s.z += v.z; s.w += v.w;
    }
    amsg[idx] = s;
}

__global__ void hpre4(const float4* __restrict__ amsg,
                      const float4* __restrict__ msg,
                      const int* __restrict__ b2a,
                      const int* __restrict__ b2revb,
                      float4* __restrict__ h)
{
    int idx = blockIdx.x * blockDim.x + threadIdx.x;
    if (idx >= N_BONDS * H4) return;
    int b = idx / H4;
    int j = idx - b * H4;
    float4 u = amsg[(size_t)b2a[b] * H4 + j];
    float4 v = msg[(size_t)b2revb[b] * H4 + j];
    float4 o = {u.x - v.x, u.y - v.y, u.z - v.z, u.w - v.w};
    h[idx] = o;
}

__global__ void concat_kernel(const float* __restrict__ f_atoms,
                              const float* __restrict__ amsg,
                              float* __restrict__ ain)
{
    int idx = blockIdx.x * blockDim.x + threadIdx.x;
    if (idx >= N_ATOMS * CAT_DIM) return;
    int a = idx / CAT_DIM;
    int k = idx - a * CAT_DIM;
    ain[idx] = (k < ATOM_FDIM) ? f_atoms[(size_t)a * ATOM_FDIM + k]
                               : amsg[(size_t)a * HID + (k - ATOM_FDIM)];
}

// ================= launch ========================================================
static inline dim3 gemm_grid(int M, int N) {
    return dim3((N + BN - 1) / BN, (M + BM - 1) / BM);
}

extern "C" void kernel_launch(void* const* d_in, const int* in_sizes, int n_in,
                              void* d_out, int out_size)
{
    const float* f_atoms = (const float*)d_in[0];
    const float* f_bonds = (const float*)d_in[1];
    const int*   a2b     = (const int*)  d_in[2];
    const int*   b2a     = (const int*)  d_in[3];
    const int*   b2revb  = (const int*)  d_in[4];
    const float* mask    = (const float*)d_in[8];
    const float* W_i     = (const float*)d_in[9];   // [300,147]
    const float* W_ih    = (const float*)d_in[10];  // [900,300]
    const float* W_hh    = (const float*)d_in[11];  // [900,300]
    const float* b_ih    = (const float*)d_in[12];
    const float* b_hh    = (const float*)d_in[13];
    const float* W_o_w   = (const float*)d_in[14];  // [300,433]
    const float* W_o_b   = (const float*)d_in[15];
    float* out = (float*)d_out;

    float *p_inp, *p_gi, *p_msg, *p_h, *p_amsg, *p_ain;
    cudaGetSymbolAddress((void**)&p_inp,  g_inp);
    cudaGetSymbolAddress((void**)&p_gi,   g_gi);
    cudaGetSymbolAddress((void**)&p_msg,  g_msg);
    cudaGetSymbolAddress((void**)&p_h,    g_h);
    cudaGetSymbolAddress((void**)&p_amsg, g_amsg);
    cudaGetSymbolAddress((void**)&p_ain,  g_ain);

    const int EW = 256;
    int nb4_grid = (N_BONDS * H4 + EW - 1) / EW;
    int na4_grid = (N_ATOMS * H4 + EW - 1) / EW;
    int cat_grid = (N_ATOMS * CAT_DIM + EW - 1) / EW;

    // inp = f_bonds @ W_i^T            [90000,300] K=147
    mma_gemm_tn<<<gemm_grid(N_BONDS, HID), 256>>>(f_bonds, W_i, nullptr, nullptr,
                                                  p_inp, N_BONDS, HID, BOND_FDIM, 0);
    // gi = inp @ W_ih^T + b_ih         [90000,900] K=300  (loop-invariant)
    mma_gemm_tn<<<gemm_grid(N_BONDS, 3 * HID), 256>>>(p_inp, W_ih, b_ih, nullptr,
                                                      p_gi, N_BONDS, 3 * HID, HID, 0);

    dim3 fgrid((HID + FBN - 1) / FBN, (N_BONDS + FBM - 1) / FBM);   // 5 x 704

    const float* msg_src = p_inp;
    for (int it = 0; it < DEPTH - 1; it++) {
        gather_sum4<<<na4_grid, EW>>>((const float4*)msg_src, a2b, (float4*)p_amsg);
        hpre4<<<nb4_grid, EW>>>((const float4*)p_amsg, (const float4*)msg_src,
                                b2a, b2revb, (float4*)p_h);
        // fused: gh = h @ W_hh^T + b_hh, then GRU -> msg
        gh_gru_fused<<<fgrid, 256>>>(p_h, W_hh, b_hh, p_gi, p_msg);
        msg_src = p_msg;
    }

    gather_sum4<<<na4_grid, EW>>>((const float4*)msg_src, a2b, (float4*)p_amsg);
    concat_kernel<<<cat_grid, EW>>>(f_atoms, p_amsg, p_ain);
    // out = relu(ain @ W_o_w^T + W_o_b) * mask   [40000,300] K=433
    mma_gemm_tn<<<gemm_grid(N_ATOMS, HID), 256>>>(p_ain, W_o_w, W_o_b, mask,
                                                  out, N_ATOMS, HID, CAT_DIM, 1);
}

// round 6
// speedup vs baseline: 1.0810x; 1.0810x over previous
#include <cuda_runtime.h>
#include <math.h>

#define N_ATOMS 40000
#define N_BONDS 90000
#define MAX_NB 6
#define ATOM_FDIM 133
#define BOND_FDIM 147
#define HID 300
#define DEPTH 6
#define CAT_DIM (ATOM_FDIM + HID)   // 433

#define H4   (HID / 4)              // 75
#define H34  (3 * HID / 4)          // 225

// ---------------- scratch (device globals; no cudaMalloc allowed) -------------
__device__ float g_inp   [N_BONDS * HID];
__device__ float g_inp_hi[N_BONDS * HID];
__device__ float g_inp_lo[N_BONDS * HID];
__device__ float g_gi    [N_BONDS * 3 * HID];
__device__ float g_msg   [N_BONDS * HID];
__device__ float g_h     [N_BONDS * HID];
__device__ float g_h_hi  [N_BONDS * HID];
__device__ float g_h_lo  [N_BONDS * HID];
__device__ float g_gh    [N_BONDS * 3 * HID];
__device__ float g_amsg  [N_ATOMS * HID];
__device__ float g_ain_hi[N_ATOMS * CAT_DIM];
__device__ float g_ain_lo[N_ATOMS * CAT_DIM];
__device__ float g_fb_hi [N_BONDS * BOND_FDIM];
__device__ float g_fb_lo [N_BONDS * BOND_FDIM];
__device__ float g_Wi_hi [HID * BOND_FDIM];
__device__ float g_Wi_lo [HID * BOND_FDIM];
__device__ float g_Wih_hi[3 * HID * HID];
__device__ float g_Wih_lo[3 * HID * HID];
__device__ float g_Whh_hi[3 * HID * HID];
__device__ float g_Whh_lo[3 * HID * HID];
__device__ float g_Wo_hi [HID * CAT_DIM];
__device__ float g_Wo_lo [HID * CAT_DIM];

// ================= helpers ======================================================
__device__ __forceinline__ unsigned smem_u32(const void* p) {
    return (unsigned)__cvta_generic_to_shared(p);
}
__device__ __forceinline__ void cp16(unsigned dst, const void* src) {
    asm volatile("cp.async.cg.shared.global [%0], [%1], 16;\n" :: "r"(dst), "l"(src));
}
__device__ __forceinline__ void cp4(unsigned dst, const void* src) {
    asm volatile("cp.async.ca.shared.global [%0], [%1], 4;\n" :: "r"(dst), "l"(src));
}
__device__ __forceinline__ void cp_commit() { asm volatile("cp.async.commit_group;\n"); }
__device__ __forceinline__ void cp_wait0()  { asm volatile("cp.async.wait_group 0;\n"); }
__device__ __forceinline__ void sts_zero16(unsigned dst) {
    asm volatile("st.shared.v4.b32 [%0], {%1,%1,%1,%1};" :: "r"(dst), "r"(0));
}
__device__ __forceinline__ void sts_zero4(unsigned dst) {
    asm volatile("st.shared.b32 [%0], %1;" :: "r"(dst), "r"(0));
}
__device__ __forceinline__ void mma_tf32(float* c, const unsigned* a, const unsigned* b) {
    asm volatile(
        "mma.sync.aligned.m16n8k8.row.col.f32.tf32.tf32.f32 "
        "{%0,%1,%2,%3},{%4,%5,%6,%7},{%8,%9},{%0,%1,%2,%3};"
        : "+f"(c[0]), "+f"(c[1]), "+f"(c[2]), "+f"(c[3])
        : "r"(a[0]), "r"(a[1]), "r"(a[2]), "r"(a[3]), "r"(b[0]), "r"(b[1]));
}
__device__ __forceinline__ void tf32_split(float v, float& hi, float& lo) {
    unsigned h;
    asm("cvt.rna.tf32.f32 %0, %1;" : "=r"(h) : "f"(v));
    hi = __uint_as_float(h);
    float l = v - hi;
    unsigned lu;
    asm("cvt.rna.tf32.f32 %0, %1;" : "=r"(lu) : "f"(l));
    lo = __uint_as_float(lu);
}
__device__ __forceinline__ float sigmoidf1(float x) { return 1.f / (1.f + expf(-x)); }

// ================= presplit 3xTF32 TN GEMM (round-3 core, no in-loop CVT) ======
// C[m,n] = sum_k A[m,k]*B[n,k] with A = Ah+Al, B = Bh+Bl (presplit tf32 pairs).
// C += Al*Bh + Ah*Bl + Ah*Bh
#define BM 128
#define BN 128
#define BK 16
#define SPAD 20
#define BUF_FLOATS (2 * BM * SPAD)       // 5120 floats per buffer
#define SMEM_BYTES (4 * BUF_FLOATS * 4)  // 81920 B

__global__ void __launch_bounds__(256)
mma_gemm_split(const float* __restrict__ Ahg, const float* __restrict__ Alg,
               const float* __restrict__ Bhg, const float* __restrict__ Blg,
               const float* __restrict__ bias, const float* __restrict__ mask,
               float* __restrict__ C, int M, int N, int K, int relu)
{
    extern __shared__ float smem[];
    float (*Ah)[BM][SPAD] = (float (*)[BM][SPAD])(smem);
    float (*Al)[BM][SPAD] = (float (*)[BM][SPAD])(smem + BUF_FLOATS);
    float (*Bh)[BM][SPAD] = (float (*)[BM][SPAD])(smem + 2 * BUF_FLOATS);
    float (*Bl)[BM][SPAD] = (float (*)[BM][SPAD])(smem + 3 * BUF_FLOATS);

    const int tid  = threadIdx.x;
    const int wid  = tid >> 5;
    const int lane = tid & 31;
    const int g = lane >> 2, t = lane & 3;
    const int warp_m = wid & 1;     // 2 warps x 64 rows
    const int warp_n = wid >> 1;    // 4 warps x 32 cols
    const int m0 = blockIdx.y * BM;
    const int n0 = blockIdx.x * BN;
    const int KT = (K + BK - 1) / BK;
    const bool vec = ((K & 3) == 0);

    float acc[4][4][4];
    #pragma unroll
    for (int mi = 0; mi < 4; mi++)
        #pragma unroll
        for (int ni = 0; ni < 4; ni++)
            #pragma unroll
            for (int r = 0; r < 4; r++) acc[mi][ni][r] = 0.f;

    auto load_tile = [&](int kt, int s) {
        const int k0 = kt * BK;
        unsigned ahb = smem_u32(&Ah[s][0][0]);
        unsigned alb = smem_u32(&Al[s][0][0]);
        unsigned bhb = smem_u32(&Bh[s][0][0]);
        unsigned blb = smem_u32(&Bl[s][0][0]);
        if (vec) {
            #pragma unroll
            for (int i = 0; i < 2; i++) {
                int idx = tid + i * 256;
                int row = idx >> 2, seg = idx & 3;
                int gk = k0 + seg * 4;
                unsigned off = (unsigned)(row * SPAD + seg * 4) * 4u;
                int gm = m0 + row, gn = n0 + row;
                if (gm < M && gk < K) {
                    size_t go = (size_t)gm * K + gk;
                    cp16(ahb + off, Ahg + go);
                    cp16(alb + off, Alg + go);
                } else { sts_zero16(ahb + off); sts_zero16(alb + off); }
                if (gn < N && gk < K) {
                    size_t go = (size_t)gn * K + gk;
                    cp16(bhb + off, Bhg + go);
                    cp16(blb + off, Blg + go);
                } else { sts_zero16(bhb + off); sts_zero16(blb + off); }
            }
        } else {
            #pragma unroll
            for (int i = 0; i < 8; i++) {
                int idx = tid + i * 256;
                int row = idx >> 4, kk = idx & 15;
                int gk = k0 + kk;
                unsigned off = (unsigned)(row * SPAD + kk) * 4u;
                int gm = m0 + row, gn = n0 + row;
                if (gm < M && gk < K) {
                    size_t go = (size_t)gm * K + gk;
                    cp4(ahb + off, Ahg + go);
                    cp4(alb + off, Alg + go);
                } else { sts_zero4(ahb + off); sts_zero4(alb + off); }
                if (gn < N && gk < K) {
                    size_t go = (size_t)gn * K + gk;
                    cp4(bhb + off, Bhg + go);
                    cp4(blb + off, Blg + go);
                } else { sts_zero4(bhb + off); sts_zero4(blb + off); }
            }
        }
    };

    load_tile(0, 0);
    cp_commit();

    for (int kt = 0; kt < KT; kt++) {
        cp_wait0();
        __syncthreads();
        const int cur = kt & 1;
        if (kt + 1 < KT) load_tile(kt + 1, cur ^ 1);
        cp_commit();

        #pragma unroll
        for (int kk = 0; kk < BK; kk += 8) {
            unsigned ah[4][4], al[4][4], bh[4][2], bl[4][2];
            #pragma unroll
            for (int mi = 0; mi < 4; mi++) {
                int m = warp_m * 64 + mi * 16;
                ah[mi][0] = __float_as_uint(Ah[cur][m + g     ][kk + t    ]);
                ah[mi][1] = __float_as_uint(Ah[cur][m + g + 8 ][kk + t    ]);
                ah[mi][2] = __float_as_uint(Ah[cur][m + g     ][kk + t + 4]);
                ah[mi][3] = __float_as_uint(Ah[cur][m + g + 8 ][kk + t + 4]);
                al[mi][0] = __float_as_uint(Al[cur][m + g     ][kk + t    ]);
                al[mi][1] = __float_as_uint(Al[cur][m + g + 8 ][kk + t    ]);
                al[mi][2] = __float_as_uint(Al[cur][m + g     ][kk + t + 4]);
                al[mi][3] = __float_as_uint(Al[cur][m + g + 8 ][kk + t + 4]);
            }
            #pragma unroll
            for (int ni = 0; ni < 4; ni++) {
                int n = warp_n * 32 + ni * 8;
                bh[ni][0] = __float_as_uint(Bh[cur][n + g][kk + t    ]);
                bh[ni][1] = __float_as_uint(Bh[cur][n + g][kk + t + 4]);
                bl[ni][0] = __float_as_uint(Bl[cur][n + g][kk + t    ]);
                bl[ni][1] = __float_as_uint(Bl[cur][n + g][kk + t + 4]);
            }
            #pragma unroll
            for (int mi = 0; mi < 4; mi++)
                #pragma unroll
                for (int ni = 0; ni < 4; ni++) {
                    mma_tf32(acc[mi][ni], al[mi], bh[ni]);
                    mma_tf32(acc[mi][ni], ah[mi], bl[ni]);
                    mma_tf32(acc[mi][ni], ah[mi], bh[ni]);
                }
        }
    }

    #pragma unroll
    for (int mi = 0; mi < 4; mi++) {
        #pragma unroll
        for (int ni = 0; ni < 4; ni++) {
            int cn = n0 + warp_n * 32 + ni * 8 + 2 * t;
            float b0 = 0.f, b1 = 0.f;
            if (bias) {
                if (cn     < N) b0 = bias[cn];
                if (cn + 1 < N) b1 = bias[cn + 1];
            }
            #pragma unroll
            for (int half = 0; half < 2; half++) {
                int rm = m0 + warp_m * 64 + mi * 16 + g + half * 8;
                if (rm >= M) continue;
                float v0 = acc[mi][ni][half * 2 + 0] + b0;
                float v1 = acc[mi][ni][half * 2 + 1] + b1;
                if (relu) { v0 = fmaxf(v0, 0.f); v1 = fmaxf(v1, 0.f); }
                if (mask) { float mk = mask[rm]; v0 *= mk; v1 *= mk; }
                if (cn + 1 < N) {
                    float2 v = {v0, v1};
                    *(float2*)(C + (size_t)rm * N + cn) = v;
                } else if (cn < N) {
                    C[(size_t)rm * N + cn] = v0;
                }
            }
        }
    }
}

// ================= split kernels ================================================
__global__ void split_kernel(const float* __restrict__ src,
                             float* __restrict__ hi, float* __restrict__ lo, int n)
{
    int idx = blockIdx.x * blockDim.x + threadIdx.x;
    if (idx >= n) return;
    float h, l;
    tf32_split(src[idx], h, l);
    hi[idx] = h;
    lo[idx] = l;
}

// ================= elementwise (float4) =========================================
__global__ void gather_sum4(const float4* __restrict__ msg,
                            const int* __restrict__ a2b,
                            float4* __restrict__ amsg)
{
    int idx = blockIdx.x * blockDim.x + threadIdx.x;
    if (idx >= N_ATOMS * H4) return;
    int a = idx / H4;
    int j = idx - a * H4;
    const int* nb = a2b + (size_t)a * MAX_NB;
    float4 s = {0.f, 0.f, 0.f, 0.f};
    #pragma unroll
    for (int i = 0; i < MAX_NB; i++) {
        float4 v = msg[(size_t)nb[i] * H4 + j];
        s.x += v.x; s.y += v.y; s.z += v.z; s.w += v.w;
    }
    amsg[idx] = s;
}

// h = amsg[b2a] - msg[b2revb]; also writes tf32 split h_hi/h_lo for the GEMM
__global__ void hpre4_split(const float4* __restrict__ amsg,
                            const float4* __restrict__ msg,
                            const int* __restrict__ b2a,
                            const int* __restrict__ b2revb,
                            float4* __restrict__ h,
                            float4* __restrict__ h_hi,
                            float4* __restrict__ h_lo)
{
    int idx = blockIdx.x * blockDim.x + threadIdx.x;
    if (idx >= N_BONDS * H4) return;
    int b = idx / H4;
    int j = idx - b * H4;
    float4 u = amsg[(size_t)b2a[b] * H4 + j];
    float4 v = msg[(size_t)b2revb[b] * H4 + j];
    float4 o = {u.x - v.x, u.y - v.y, u.z - v.z, u.w - v.w};
    float4 oh, ol;
    tf32_split(o.x, oh.x, ol.x);
    tf32_split(o.y, oh.y, ol.y);
    tf32_split(o.z, oh.z, ol.z);
    tf32_split(o.w, oh.w, ol.w);
    h[idx] = o;
    h_hi[idx] = oh;
    h_lo[idx] = ol;
}

__global__ void gru4(const float4* __restrict__ gi,
                     const float4* __restrict__ gh,
                     const float4* __restrict__ h,
                     float4* __restrict__ out)
{
    int idx = blockIdx.x * blockDim.x + threadIdx.x;
    if (idx >= N_BONDS * H4) return;
    int b = idx / H4;
    int j = idx - b * H4;
    if (b == 0) { out[idx] = make_float4(0.f, 0.f, 0.f, 0.f); return; }
    size_t gb = (size_t)b * H34;
    float4 ir = gi[gb + j], iz = gi[gb + H4 + j], in4 = gi[gb + 2 * H4 + j];
    float4 hr = gh[gb + j], hz = gh[gb + H4 + j], hn4 = gh[gb + 2 * H4 + j];
    float4 hh = h[idx];
    float4 o;
    {
        float r = sigmoidf1(ir.x + hr.x), z = sigmoidf1(iz.x + hz.x);
        float n = tanhf(in4.x + r * hn4.x);
        o.x = (1.f - z) * n + z * hh.x;
    }
    {
        float r = sigmoidf1(ir.y + hr.y), z = sigmoidf1(iz.y + hz.y);
        float n = tanhf(in4.y + r * hn4.y);
        o.y = (1.f - z) * n + z * hh.y;
    }
    {
        float r = sigmoidf1(ir.z + hr.z), z = sigmoidf1(iz.z + hz.z);
        float n = tanhf(in4.z + r * hn4.z);
        o.z = (1.f - z) * n + z * hh.z;
    }
    {
        float r = sigmoidf1(ir.w + hr.w), z = sigmoidf1(iz.w + hz.w);
        float n = tanhf(in4.w + r * hn4.w);
        o.w = (1.f - z) * n + z * hh.w;
    }
    out[idx] = o;
}

// concat directly into split form (ain used only as GEMM A operand)
__global__ void concat_split(const float* __restrict__ f_atoms,
                             const float* __restrict__ amsg,
                             float* __restrict__ ain_hi,
                             float* __restrict__ ain_lo)
{
    int idx = blockIdx.x * blockDim.x + threadIdx.x;
    if (idx >= N_ATOMS * CAT_DIM) return;
    int a = idx / CAT_DIM;
    int k = idx - a * CAT_DIM;
    float v = (k < ATOM_FDIM) ? f_atoms[(size_t)a * ATOM_FDIM + k]
                              : amsg[(size_t)a * HID + (k - ATOM_FDIM)];
    float h, l;
    tf32_split(v, h, l);
    ain_hi[idx] = h;
    ain_lo[idx] = l;
}

// ================= launch ========================================================
static inline dim3 gemm_grid(int M, int N) {
    return dim3((N + BN - 1) / BN, (M + BM - 1) / BM);
}

extern "C" void kernel_launch(void* const* d_in, const int* in_sizes, int n_in,
                              void* d_out, int out_size)
{
    const float* f_atoms = (const float*)d_in[0];
    const float* f_bonds = (const float*)d_in[1];
    const int*   a2b     = (const int*)  d_in[2];
    const int*   b2a     = (const int*)  d_in[3];
    const int*   b2revb  = (const int*)  d_in[4];
    const float* mask    = (const float*)d_in[8];
    const float* W_i     = (const float*)d_in[9];   // [300,147]
    const float* W_ih    = (const float*)d_in[10];  // [900,300]
    const float* W_hh    = (const float*)d_in[11];  // [900,300]
    const float* b_ih    = (const float*)d_in[12];
    const float* b_hh    = (const float*)d_in[13];
    const float* W_o_w   = (const float*)d_in[14];  // [300,433]
    const float* W_o_b   = (const float*)d_in[15];
    float* out = (float*)d_out;

    float *p_inp, *p_inp_hi, *p_inp_lo, *p_gi, *p_msg, *p_h, *p_h_hi, *p_h_lo;
    float *p_gh, *p_amsg, *p_ain_hi, *p_ain_lo, *p_fb_hi, *p_fb_lo;
    float *p_Wi_hi, *p_Wi_lo, *p_Wih_hi, *p_Wih_lo, *p_Whh_hi, *p_Whh_lo, *p_Wo_hi, *p_Wo_lo;
    cudaGetSymbolAddress((void**)&p_inp,    g_inp);
    cudaGetSymbolAddress((void**)&p_inp_hi, g_inp_hi);
    cudaGetSymbolAddress((void**)&p_inp_lo, g_inp_lo);
    cudaGetSymbolAddress((void**)&p_gi,     g_gi);
    cudaGetSymbolAddress((void**)&p_msg,    g_msg);
    cudaGetSymbolAddress((void**)&p_h,      g_h);
    cudaGetSymbolAddress((void**)&p_h_hi,   g_h_hi);
    cudaGetSymbolAddress((void**)&p_h_lo,   g_h_lo);
    cudaGetSymbolAddress((void**)&p_gh,     g_gh);
    cudaGetSymbolAddress((void**)&p_amsg,   g_amsg);
    cudaGetSymbolAddress((void**)&p_ain_hi, g_ain_hi);
    cudaGetSymbolAddress((void**)&p_ain_lo, g_ain_lo);
    cudaGetSymbolAddress((void**)&p_fb_hi,  g_fb_hi);
    cudaGetSymbolAddress((void**)&p_fb_lo,  g_fb_lo);
    cudaGetSymbolAddress((void**)&p_Wi_hi,  g_Wi_hi);
    cudaGetSymbolAddress((void**)&p_Wi_lo,  g_Wi_lo);
    cudaGetSymbolAddress((void**)&p_Wih_hi, g_Wih_hi);
    cudaGetSymbolAddress((void**)&p_Wih_lo, g_Wih_lo);
    cudaGetSymbolAddress((void**)&p_Whh_hi, g_Whh_hi);
    cudaGetSymbolAddress((void**)&p_Whh_lo, g_Whh_lo);
    cudaGetSymbolAddress((void**)&p_Wo_hi,  g_Wo_hi);
    cudaGetSymbolAddress((void**)&p_Wo_lo,  g_Wo_lo);

    static bool attr_set = false;
    if (!attr_set) {
        cudaFuncSetAttribute(mma_gemm_split,
                             cudaFuncAttributeMaxDynamicSharedMemorySize, SMEM_BYTES);
        attr_set = true;
    }

    const int EW = 256;
    int nb4_grid = (N_BONDS * H4 + EW - 1) / EW;
    int na4_grid = (N_ATOMS * H4 + EW - 1) / EW;
    int cat_grid = (N_ATOMS * CAT_DIM + EW - 1) / EW;
    auto sgrid = [](int n) { return (n + 255) / 256; };

    // ---- one-shot splits: weights + f_bonds
    split_kernel<<<sgrid(N_BONDS * BOND_FDIM), 256>>>(f_bonds, p_fb_hi, p_fb_lo, N_BONDS * BOND_FDIM);
    split_kernel<<<sgrid(HID * BOND_FDIM),     256>>>(W_i,   p_Wi_hi,  p_Wi_lo,  HID * BOND_FDIM);
    split_kernel<<<sgrid(3 * HID * HID),       256>>>(W_ih,  p_Wih_hi, p_Wih_lo, 3 * HID * HID);
    split_kernel<<<sgrid(3 * HID * HID),       256>>>(W_hh,  p_Whh_hi, p_Whh_lo, 3 * HID * HID);
    split_kernel<<<sgrid(HID * CAT_DIM),       256>>>(W_o_w, p_Wo_hi,  p_Wo_lo,  HID * CAT_DIM);

    // inp = f_bonds @ W_i^T            [90000,300] K=147
    mma_gemm_split<<<gemm_grid(N_BONDS, HID), 256, SMEM_BYTES>>>(
        p_fb_hi, p_fb_lo, p_Wi_hi, p_Wi_lo, nullptr, nullptr,
        p_inp, N_BONDS, HID, BOND_FDIM, 0);

    // split inp (A operand of gi GEMM)
    split_kernel<<<sgrid(N_BONDS * HID), 256>>>(p_inp, p_inp_hi, p_inp_lo, N_BONDS * HID);

    // gi = inp @ W_ih^T + b_ih         [90000,900] K=300  (loop-invariant)
    mma_gemm_split<<<gemm_grid(N_BONDS, 3 * HID), 256, SMEM_BYTES>>>(
        p_inp_hi, p_inp_lo, p_Wih_hi, p_Wih_lo, b_ih, nullptr,
        p_gi, N_BONDS, 3 * HID, HID, 0);

    const float* msg_src = p_inp;
    for (int it = 0; it < DEPTH - 1; it++) {
        gather_sum4<<<na4_grid, EW>>>((const float4*)msg_src, a2b, (float4*)p_amsg);
        hpre4_split<<<nb4_grid, EW>>>((const float4*)p_amsg, (const float4*)msg_src,
                                      b2a, b2revb,
                                      (float4*)p_h, (float4*)p_h_hi, (float4*)p_h_lo);
        // gh = h @ W_hh^T + b_hh       [90000,900] K=300
        mma_gemm_split<<<gemm_grid(N_BONDS, 3 * HID), 256, SMEM_BYTES>>>(
            p_h_hi, p_h_lo, p_Whh_hi, p_Whh_lo, b_hh, nullptr,
            p_gh, N_BONDS, 3 * HID, HID, 0);
        gru4<<<nb4_grid, EW>>>((const float4*)p_gi, (const float4*)p_gh,
                               (const float4*)p_h, (float4*)p_msg);
        msg_src = p_msg;
    }

    gather_sum4<<<na4_grid, EW>>>((const float4*)msg_src, a2b, (float4*)p_amsg);
    concat_split<<<cat_grid, EW>>>(f_atoms, p_amsg, p_ain_hi, p_ain_lo);
    // out = relu(ain @ W_o_w^T + W_o_b) * mask   [40000,300] K=433
    mma_gemm_split<<<gemm_grid(N_ATOMS, HID), 256, SMEM_BYTES>>>(
        p_ain_hi, p_ain_lo, p_Wo_hi, p_Wo_lo, W_o_b, mask,
        out, N_ATOMS, HID, CAT_DIM, 1);
}

// round 7
// speedup vs baseline: 1.8839x; 1.7427x over previous
#include <cuda_runtime.h>
#include <cuda_bf16.h>
#include <math.h>

#define N_ATOMS 40000
#define N_BONDS 90000
#define MAX_NB 6
#define ATOM_FDIM 133
#define BOND_FDIM 147
#define HID 300
#define DEPTH 6
#define CAT_DIM (ATOM_FDIM + HID)   // 433

#define H4   (HID / 4)              // 75
#define H34  (3 * HID / 4)          // 225

// padded K strides (multiples of 32) for bf16 split operands
#define KP_BOND 160                 // 147 -> 160
#define KP_HID  320                 // 300 -> 320
#define KP_CAT  448                 // 433 -> 448

// ---------------- scratch (device globals; no cudaMalloc allowed) -------------
__device__ float g_inp [N_BONDS * HID];
__device__ float g_gi  [N_BONDS * 3 * HID];
__device__ float g_msg [N_BONDS * HID];
__device__ float g_h   [N_BONDS * HID];
__device__ float g_gh  [N_BONDS * 3 * HID];
__device__ float g_amsg[N_ATOMS * HID];

__device__ __nv_bfloat16 g_fb_hi [N_BONDS * KP_BOND];
__device__ __nv_bfloat16 g_fb_lo [N_BONDS * KP_BOND];
__device__ __nv_bfloat16 g_inp_hi[N_BONDS * KP_HID];
__device__ __nv_bfloat16 g_inp_lo[N_BONDS * KP_HID];
__device__ __nv_bfloat16 g_h_hi  [N_BONDS * KP_HID];
__device__ __nv_bfloat16 g_h_lo  [N_BONDS * KP_HID];
__device__ __nv_bfloat16 g_ain_hi[N_ATOMS * KP_CAT];
__device__ __nv_bfloat16 g_ain_lo[N_ATOMS * KP_CAT];
__device__ __nv_bfloat16 g_Wi_hi [HID * KP_BOND];
__device__ __nv_bfloat16 g_Wi_lo [HID * KP_BOND];
__device__ __nv_bfloat16 g_Wih_hi[3 * HID * KP_HID];
__device__ __nv_bfloat16 g_Wih_lo[3 * HID * KP_HID];
__device__ __nv_bfloat16 g_Whh_hi[3 * HID * KP_HID];
__device__ __nv_bfloat16 g_Whh_lo[3 * HID * KP_HID];
__device__ __nv_bfloat16 g_Wo_hi [HID * KP_CAT];
__device__ __nv_bfloat16 g_Wo_lo [HID * KP_CAT];

// ================= helpers ======================================================
__device__ __forceinline__ unsigned smem_u32(const void* p) {
    return (unsigned)__cvta_generic_to_shared(p);
}
__device__ __forceinline__ void cp16(unsigned dst, const void* src) {
    asm volatile("cp.async.cg.shared.global [%0], [%1], 16;\n" :: "r"(dst), "l"(src));
}
__device__ __forceinline__ void cp_commit() { asm volatile("cp.async.commit_group;\n"); }
__device__ __forceinline__ void cp_wait0()  { asm volatile("cp.async.wait_group 0;\n"); }
__device__ __forceinline__ void sts_zero16(unsigned dst) {
    asm volatile("st.shared.v4.b32 [%0], {%1,%1,%1,%1};" :: "r"(dst), "r"(0));
}
__device__ __forceinline__ void ldsm_x4(unsigned& r0, unsigned& r1, unsigned& r2,
                                        unsigned& r3, unsigned addr) {
    asm volatile("ldmatrix.sync.aligned.m8n8.x4.shared.b16 {%0,%1,%2,%3}, [%4];"
                 : "=r"(r0), "=r"(r1), "=r"(r2), "=r"(r3) : "r"(addr));
}
__device__ __forceinline__ void mma_bf16(float* c, const unsigned* a, const unsigned* b) {
    asm volatile(
        "mma.sync.aligned.m16n8k16.row.col.f32.bf16.bf16.f32 "
        "{%0,%1,%2,%3},{%4,%5,%6,%7},{%8,%9},{%0,%1,%2,%3};"
        : "+f"(c[0]), "+f"(c[1]), "+f"(c[2]), "+f"(c[3])
        : "r"(a[0]), "r"(a[1]), "r"(a[2]), "r"(a[3]), "r"(b[0]), "r"(b[1]));
}
__device__ __forceinline__ void bf16_split(float v, __nv_bfloat16& hi, __nv_bfloat16& lo) {
    hi = __float2bfloat16_rn(v);
    lo = __float2bfloat16_rn(v - __bfloat162float(hi));
}
__device__ __forceinline__ float sigmoidf1(float x) { return 1.f / (1.f + expf(-x)); }

// ================= bf16x3 TN GEMM ===============================================
// C[m,n] = sum_k A[m,k]*B[n,k], A = Ah+Al, B = Bh+Bl (bf16 2-term splits).
// C += Al*Bh + Ah*Bl + Ah*Bh  (fp32 accumulate)
#define BM 128
#define BN 128
#define BK 32
#define ROWS 40                      // smem row stride in bf16 (32 + 8 pad)
#define BUF_ELEMS (2 * BM * ROWS)    // per buffer, 2 stages = 10240 bf16
#define SMEM_BYTES (4 * BUF_ELEMS * 2)  // 81920 B

__global__ void __launch_bounds__(256)
mma_gemm_bf16x3(const __nv_bfloat16* __restrict__ Ahg, const __nv_bfloat16* __restrict__ Alg,
                const __nv_bfloat16* __restrict__ Bhg, const __nv_bfloat16* __restrict__ Blg,
                const float* __restrict__ bias, const float* __restrict__ mask,
                float* __restrict__ C, int M, int N, int KT, int KP, int relu)
{
    extern __shared__ __nv_bfloat16 smem[];
    __nv_bfloat16* Ah = smem;
    __nv_bfloat16* Al = smem + BUF_ELEMS;
    __nv_bfloat16* Bh = smem + 2 * BUF_ELEMS;
    __nv_bfloat16* Bl = smem + 3 * BUF_ELEMS;

    const int tid  = threadIdx.x;
    const int wid  = tid >> 5;
    const int lane = tid & 31;
    const int warp_m = wid & 1;     // 2 warps x 64 rows
    const int warp_n = wid >> 1;    // 4 warps x 32 cols
    const int m0 = blockIdx.y * BM;
    const int n0 = blockIdx.x * BN;
    const int mat = lane >> 3;      // ldmatrix address groups
    const int rw  = lane & 7;

    float acc[4][4][4];
    #pragma unroll
    for (int mi = 0; mi < 4; mi++)
        #pragma unroll
        for (int ni = 0; ni < 4; ni++)
            #pragma unroll
            for (int r = 0; r < 4; r++) acc[mi][ni][r] = 0.f;

    // tile load: per buffer, 512 chunks of 8 bf16 (16B); 2 per thread
    auto load_tile = [&](int kt, int s) {
        const int k0 = kt * BK;
        const int sb = s * BM * ROWS;
        #pragma unroll
        for (int i = 0; i < 2; i++) {
            int idx = tid + i * 256;
            int row = idx >> 2, seg = idx & 3;
            int kc = seg * 8;
            unsigned offA = smem_u32(&Ah[sb + row * ROWS + kc]);
            unsigned offAl = smem_u32(&Al[sb + row * ROWS + kc]);
            unsigned offB = smem_u32(&Bh[sb + row * ROWS + kc]);
            unsigned offBl = smem_u32(&Bl[sb + row * ROWS + kc]);
            int gm = m0 + row, gn = n0 + row;
            if (gm < M) {
                size_t go = (size_t)gm * KP + k0 + kc;
                cp16(offA, Ahg + go);
                cp16(offAl, Alg + go);
            } else { sts_zero16(offA); sts_zero16(offAl); }
            if (gn < N) {
                size_t go = (size_t)gn * KP + k0 + kc;
                cp16(offB, Bhg + go);
                cp16(offBl, Blg + go);
            } else { sts_zero16(offB); sts_zero16(offBl); }
        }
    };

    load_tile(0, 0);
    cp_commit();

    for (int kt = 0; kt < KT; kt++) {
        cp_wait0();
        __syncthreads();
        const int cur = kt & 1;
        if (kt + 1 < KT) load_tile(kt + 1, cur ^ 1);
        cp_commit();
        const int sb = cur * BM * ROWS;

        #pragma unroll
        for (int kk = 0; kk < BK; kk += 16) {
            // A fragments: per mi, ldmatrix.x4 (16 rows x 16 k)
            unsigned ah[4][4], al[4][4];
            #pragma unroll
            for (int mi = 0; mi < 4; mi++) {
                int arow = warp_m * 64 + mi * 16 + ((mat & 1) << 3) + rw;
                int acol = kk + ((mat >> 1) << 3);
                unsigned ad = smem_u32(&Ah[sb + arow * ROWS + acol]);
                ldsm_x4(ah[mi][0], ah[mi][1], ah[mi][2], ah[mi][3], ad);
                unsigned ad2 = smem_u32(&Al[sb + arow * ROWS + acol]);
                ldsm_x4(al[mi][0], al[mi][1], al[mi][2], al[mi][3], ad2);
            }
            // B fragments: per 16-col group, ldmatrix.x4 covers two n8 tiles
            unsigned bh[4][2], bl[4][2];
            #pragma unroll
            for (int ni2 = 0; ni2 < 2; ni2++) {
                int brow = warp_n * 32 + ni2 * 16 + ((mat >> 1) << 3) + rw;
                int bcol = kk + ((mat & 1) << 3);
                unsigned r0, r1, r2, r3;
                unsigned bd = smem_u32(&Bh[sb + brow * ROWS + bcol]);
                ldsm_x4(r0, r1, r2, r3, bd);
                bh[ni2*2  ][0] = r0; bh[ni2*2  ][1] = r1;
                bh[ni2*2+1][0] = r2; bh[ni2*2+1][1] = r3;
                unsigned bd2 = smem_u32(&Bl[sb + brow * ROWS + bcol]);
                ldsm_x4(r0, r1, r2, r3, bd2);
                bl[ni2*2  ][0] = r0; bl[ni2*2  ][1] = r1;
                bl[ni2*2+1][0] = r2; bl[ni2*2+1][1] = r3;
            }
            #pragma unroll
            for (int mi = 0; mi < 4; mi++)
                #pragma unroll
                for (int ni = 0; ni < 4; ni++) {
                    mma_bf16(acc[mi][ni], al[mi], bh[ni]);   // lo*hi
                    mma_bf16(acc[mi][ni], ah[mi], bl[ni]);   // hi*lo
                    mma_bf16(acc[mi][ni], ah[mi], bh[ni]);   // hi*hi
                }
        }
        __syncthreads();
    }

    // epilogue (same c-frag layout as before)
    const int g = lane >> 2, t = lane & 3;
    #pragma unroll
    for (int mi = 0; mi < 4; mi++) {
        #pragma unroll
        for (int ni = 0; ni < 4; ni++) {
            int cn = n0 + warp_n * 32 + ni * 8 + 2 * t;
            float b0 = 0.f, b1 = 0.f;
            if (bias) {
                if (cn     < N) b0 = bias[cn];
                if (cn + 1 < N) b1 = bias[cn + 1];
            }
            #pragma unroll
            for (int half = 0; half < 2; half++) {
                int rm = m0 + warp_m * 64 + mi * 16 + g + half * 8;
                if (rm >= M) continue;
                float v0 = acc[mi][ni][half * 2 + 0] + b0;
                float v1 = acc[mi][ni][half * 2 + 1] + b1;
                if (relu) { v0 = fmaxf(v0, 0.f); v1 = fmaxf(v1, 0.f); }
                if (mask) { float mk = mask[rm]; v0 *= mk; v1 *= mk; }
                if (cn + 1 < N) {
                    float2 v = {v0, v1};
                    *(float2*)(C + (size_t)rm * N + cn) = v;
                } else if (cn < N) {
                    C[(size_t)rm * N + cn] = v0;
                }
            }
        }
    }
}

// ================= split producers ==============================================
// fp32 [M][K] -> bf16 hi/lo [M][KP], zero-padding k in [K, KP)
__global__ void split_bf16(const float* __restrict__ src,
                           __nv_bfloat16* __restrict__ hi,
                           __nv_bfloat16* __restrict__ lo,
                           int M, int K, int KP)
{
    int idx = blockIdx.x * blockDim.x + threadIdx.x;
    if (idx >= M * KP) return;
    int m = idx / KP;
    int k = idx - m * KP;
    float v = (k < K) ? src[(size_t)m * K + k] : 0.f;
    __nv_bfloat16 h, l;
    bf16_split(v, h, l);
    hi[idx] = h;
    lo[idx] = l;
}

// zero the pad columns [HID, KP_HID) of h_hi/h_lo (hpre only writes k < HID)
__global__ void zero_pad_h(__nv_bfloat16* __restrict__ hi, __nv_bfloat16* __restrict__ lo)
{
    int idx = blockIdx.x * blockDim.x + threadIdx.x;
    const int PADW = KP_HID - HID;   // 20
    if (idx >= N_BONDS * PADW) return;
    int b = idx / PADW;
    int k = HID + (idx - b * PADW);
    hi[(size_t)b * KP_HID + k] = __float2bfloat16(0.f);
    lo[(size_t)b * KP_HID + k] = __float2bfloat16(0.f);
}

// ================= elementwise ==================================================
__global__ void gather_sum4(const float4* __restrict__ msg,
                            const int* __restrict__ a2b,
                            float4* __restrict__ amsg)
{
    int idx = blockIdx.x * blockDim.x + threadIdx.x;
    if (idx >= N_ATOMS * H4) return;
    int a = idx / H4;
    int j = idx - a * H4;
    const int* nb = a2b + (size_t)a * MAX_NB;
    float4 s = {0.f, 0.f, 0.f, 0.f};
    #pragma unroll
    for (int i = 0; i < MAX_NB; i++) {
        float4 v = msg[(size_t)nb[i] * H4 + j];
        s.x += v.x; s.y += v.y; s.z += v.z; s.w += v.w;
    }
    amsg[idx] = s;
}

// h = amsg[b2a] - msg[b2revb]; writes fp32 h and bf16 hi/lo (padded stride)
__global__ void hpre4_split(const float4* __restrict__ amsg,
                            const float4* __restrict__ msg,
                            const int* __restrict__ b2a,
                            const int* __restrict__ b2revb,
                            float4* __restrict__ h,
                            __nv_bfloat162* __restrict__ h_hi,
                            __nv_bfloat162* __restrict__ h_lo)
{
    int idx = blockIdx.x * blockDim.x + threadIdx.x;
    if (idx >= N_BONDS * H4) return;
    int b = idx / H4;
    int j = idx - b * H4;
    float4 u = amsg[(size_t)b2a[b] * H4 + j];
    float4 v = msg[(size_t)b2revb[b] * H4 + j];
    float4 o = {u.x - v.x, u.y - v.y, u.z - v.z, u.w - v.w};
    h[idx] = o;
    __nv_bfloat16 hx, lx, hy, ly, hz, lz, hw, lw;
    bf16_split(o.x, hx, lx);
    bf16_split(o.y, hy, ly);
    bf16_split(o.z, hz, lz);
    bf16_split(o.w, hw, lw);
    size_t base = (size_t)b * (KP_HID / 2) + j * 2;
    h_hi[base]     = __nv_bfloat162(hx, hy);
    h_hi[base + 1] = __nv_bfloat162(hz, hw);
    h_lo[base]     = __nv_bfloat162(lx, ly);
    h_lo[base + 1] = __nv_bfloat162(lz, lw);
}

__global__ void gru4(const float4* __restrict__ gi,
                     const float4* __restrict__ gh,
                     const float4* __restrict__ h,
                     float4* __restrict__ out)
{
    int idx = blockIdx.x * blockDim.x + threadIdx.x;
    if (idx >= N_BONDS * H4) return;
    int b = idx / H4;
    int j = idx - b * H4;
    if (b == 0) { out[idx] = make_float4(0.f, 0.f, 0.f, 0.f); return; }
    size_t gb = (size_t)b * H34;
    float4 ir = gi[gb + j], iz = gi[gb + H4 + j], in4 = gi[gb + 2 * H4 + j];
    float4 hr = gh[gb + j], hz = gh[gb + H4 + j], hn4 = gh[gb + 2 * H4 + j];
    float4 hh = h[idx];
    float4 o;
    {
        float r = sigmoidf1(ir.x + hr.x), z = sigmoidf1(iz.x + hz.x);
        float n = tanhf(in4.x + r * hn4.x);
        o.x = (1.f - z) * n + z * hh.x;
    }
    {
        float r = sigmoidf1(ir.y + hr.y), z = sigmoidf1(iz.y + hz.y);
        float n = tanhf(in4.y + r * hn4.y);
        o.y = (1.f - z) * n + z * hh.y;
    }
    {
        float r = sigmoidf1(ir.z + hr.z), z = sigmoidf1(iz.z + hz.z);
        float n = tanhf(in4.z + r * hn4.z);
        o.z = (1.f - z) * n + z * hh.z;
    }
    {
        float r = sigmoidf1(ir.w + hr.w), z = sigmoidf1(iz.w + hz.w);
        float n = tanhf(in4.w + r * hn4.w);
        o.w = (1.f - z) * n + z * hh.w;
    }
    out[idx] = o;
}

// concat(f_atoms, amsg) directly into split bf16 (padded to KP_CAT)
__global__ void concat_split(const float* __restrict__ f_atoms,
                             const float* __restrict__ amsg,
                             __nv_bfloat16* __restrict__ ain_hi,
                             __nv_bfloat16* __restrict__ ain_lo)
{
    int idx = blockIdx.x * blockDim.x + threadIdx.x;
    if (idx >= N_ATOMS * KP_CAT) return;
    int a = idx / KP_CAT;
    int k = idx - a * KP_CAT;
    float v = 0.f;
    if (k < ATOM_FDIM)      v = f_atoms[(size_t)a * ATOM_FDIM + k];
    else if (k < CAT_DIM)   v = amsg[(size_t)a * HID + (k - ATOM_FDIM)];
    __nv_bfloat16 h, l;
    bf16_split(v, h, l);
    ain_hi[idx] = h;
    ain_lo[idx] = l;
}

// ================= launch ========================================================
static inline dim3 gemm_grid(int M, int N) {
    return dim3((N + BN - 1) / BN, (M + BM - 1) / BM);
}

extern "C" void kernel_launch(void* const* d_in, const int* in_sizes, int n_in,
                              void* d_out, int out_size)
{
    const float* f_atoms = (const float*)d_in[0];
    const float* f_bonds = (const float*)d_in[1];
    const int*   a2b     = (const int*)  d_in[2];
    const int*   b2a     = (const int*)  d_in[3];
    const int*   b2revb  = (const int*)  d_in[4];
    const float* mask    = (const float*)d_in[8];
    const float* W_i     = (const float*)d_in[9];   // [300,147]
    const float* W_ih    = (const float*)d_in[10];  // [900,300]
    const float* W_hh    = (const float*)d_in[11];  // [900,300]
    const float* b_ih    = (const float*)d_in[12];
    const float* b_hh    = (const float*)d_in[13];
    const float* W_o_w   = (const float*)d_in[14];  // [300,433]
    const float* W_o_b   = (const float*)d_in[15];
    float* out = (float*)d_out;

    float *p_inp, *p_gi, *p_msg, *p_h, *p_gh, *p_amsg;
    __nv_bfloat16 *p_fb_hi, *p_fb_lo, *p_inp_hi, *p_inp_lo, *p_h_hi, *p_h_lo;
    __nv_bfloat16 *p_ain_hi, *p_ain_lo;
    __nv_bfloat16 *p_Wi_hi, *p_Wi_lo, *p_Wih_hi, *p_Wih_lo, *p_Whh_hi, *p_Whh_lo;
    __nv_bfloat16 *p_Wo_hi, *p_Wo_lo;
    cudaGetSymbolAddress((void**)&p_inp,    g_inp);
    cudaGetSymbolAddress((void**)&p_gi,     g_gi);
    cudaGetSymbolAddress((void**)&p_msg,    g_msg);
    cudaGetSymbolAddress((void**)&p_h,      g_h);
    cudaGetSymbolAddress((void**)&p_gh,     g_gh);
    cudaGetSymbolAddress((void**)&p_amsg,   g_amsg);
    cudaGetSymbolAddress((void**)&p_fb_hi,  g_fb_hi);
    cudaGetSymbolAddress((void**)&p_fb_lo,  g_fb_lo);
    cudaGetSymbolAddress((void**)&p_inp_hi, g_inp_hi);
    cudaGetSymbolAddress((void**)&p_inp_lo, g_inp_lo);
    cudaGetSymbolAddress((void**)&p_h_hi,   g_h_hi);
    cudaGetSymbolAddress((void**)&p_h_lo,   g_h_lo);
    cudaGetSymbolAddress((void**)&p_ain_hi, g_ain_hi);
    cudaGetSymbolAddress((void**)&p_ain_lo, g_ain_lo);
    cudaGetSymbolAddress((void**)&p_Wi_hi,  g_Wi_hi);
    cudaGetSymbolAddress((void**)&p_Wi_lo,  g_Wi_lo);
    cudaGetSymbolAddress((void**)&p_Wih_hi, g_Wih_hi);
    cudaGetSymbolAddress((void**)&p_Wih_lo, g_Wih_lo);
    cudaGetSymbolAddress((void**)&p_Whh_hi, g_Whh_hi);
    cudaGetSymbolAddress((void**)&p_Whh_lo, g_Whh_lo);
    cudaGetSymbolAddress((void**)&p_Wo_hi,  g_Wo_hi);
    cudaGetSymbolAddress((void**)&p_Wo_lo,  g_Wo_lo);

    static bool attr_set = false;
    if (!attr_set) {
        cudaFuncSetAttribute(mma_gemm_bf16x3,
                             cudaFuncAttributeMaxDynamicSharedMemorySize, SMEM_BYTES);
        attr_set = true;
    }

    const int EW = 256;
    int nb4_grid = (N_BONDS * H4 + EW - 1) / EW;
    int na4_grid = (N_ATOMS * H4 + EW - 1) / EW;
    auto sgrid = [](long n) { return (int)((n + 255) / 256); };

    // ---- one-shot splits (weights + f_bonds) + h pad zero
    split_bf16<<<sgrid((long)N_BONDS * KP_BOND), 256>>>(f_bonds, p_fb_hi, p_fb_lo,
                                                        N_BONDS, BOND_FDIM, KP_BOND);
    split_bf16<<<sgrid((long)HID * KP_BOND), 256>>>(W_i, p_Wi_hi, p_Wi_lo,
                                                    HID, BOND_FDIM, KP_BOND);
    split_bf16<<<sgrid((long)3 * HID * KP_HID), 256>>>(W_ih, p_Wih_hi, p_Wih_lo,
                                                       3 * HID, HID, KP_HID);
    split_bf16<<<sgrid((long)3 * HID * KP_HID), 256>>>(W_hh, p_Whh_hi, p_Whh_lo,
                                                       3 * HID, HID, KP_HID);
    split_bf16<<<sgrid((long)HID * KP_CAT), 256>>>(W_o_w, p_Wo_hi, p_Wo_lo,
                                                   HID, CAT_DIM, KP_CAT);
    zero_pad_h<<<sgrid((long)N_BONDS * (KP_HID - HID)), 256>>>(p_h_hi, p_h_lo);

    // inp = f_bonds @ W_i^T            [90000,300] K=147 (KT=5)
    mma_gemm_bf16x3<<<gemm_grid(N_BONDS, HID), 256, SMEM_BYTES>>>(
        p_fb_hi, p_fb_lo, p_Wi_hi, p_Wi_lo, nullptr, nullptr,
        p_inp, N_BONDS, HID, KP_BOND / BK, KP_BOND, 0);

    // split inp for the gi GEMM
    split_bf16<<<sgrid((long)N_BONDS * KP_HID), 256>>>(p_inp, p_inp_hi, p_inp_lo,
                                                       N_BONDS, HID, KP_HID);

    // gi = inp @ W_ih^T + b_ih         [90000,900] K=300 (KT=10)
    mma_gemm_bf16x3<<<gemm_grid(N_BONDS, 3 * HID), 256, SMEM_BYTES>>>(
        p_inp_hi, p_inp_lo, p_Wih_hi, p_Wih_lo, b_ih, nullptr,
        p_gi, N_BONDS, 3 * HID, KP_HID / BK, KP_HID, 0);

    const float* msg_src = p_inp;
    for (int it = 0; it < DEPTH - 1; it++) {
        gather_sum4<<<na4_grid, EW>>>((const float4*)msg_src, a2b, (float4*)p_amsg);
        hpre4_split<<<nb4_grid, EW>>>((const float4*)p_amsg, (const float4*)msg_src,
                                      b2a, b2revb, (float4*)p_h,
                                      (__nv_bfloat162*)p_h_hi, (__nv_bfloat162*)p_h_lo);
        // gh = h @ W_hh^T + b_hh       [90000,900] K=300
        mma_gemm_bf16x3<<<gemm_grid(N_BONDS, 3 * HID), 256, SMEM_BYTES>>>(
            p_h_hi, p_h_lo, p_Whh_hi, p_Whh_lo, b_hh, nullptr,
            p_gh, N_BONDS, 3 * HID, KP_HID / BK, KP_HID, 0);
        gru4<<<nb4_grid, EW>>>((const float4*)p_gi, (const float4*)p_gh,
                               (const float4*)p_h, (float4*)p_msg);
        msg_src = p_msg;
    }

    gather_sum4<<<na4_grid, EW>>>((const float4*)msg_src, a2b, (float4*)p_amsg);
    concat_split<<<sgrid((long)N_ATOMS * KP_CAT), 256>>>(f_atoms, p_amsg,
                                                         p_ain_hi, p_ain_lo);
    // out = relu(ain @ W_o_w^T + W_o_b) * mask   [40000,300] K=433 (KT=14)
    mma_gemm_bf16x3<<<gemm_grid(N_ATOMS, HID), 256, SMEM_BYTES>>>(
        p_ain_hi, p_ain_lo, p_Wo_hi, p_Wo_lo, W_o_b, mask,
        out, N_ATOMS, HID, KP_CAT / BK, KP_CAT, 1);
}

// round 9
// speedup vs baseline: 1.9097x; 1.0137x over previous
#include <cuda_runtime.h>
#include <cuda_bf16.h>
#include <math.h>
#include <stdint.h>

#define N_ATOMS 40000
#define N_BONDS 90000
#define MAX_NB 6
#define ATOM_FDIM 133
#define BOND_FDIM 147
#define HID 300
#define DEPTH 6
#define CAT_DIM (ATOM_FDIM + HID)   // 433

#define H4   (HID / 4)              // 75
#define H34  (3 * HID / 4)          // 225

// padded K strides (multiples of 32) for bf16 split operands
#define KP_BOND 160                 // 147 -> 160
#define KP_HID  320                 // 300 -> 320
#define KP_CAT  448                 // 433 -> 448

// ---------------- scratch (device globals; no cudaMalloc allowed) -------------
__device__ float g_inp [N_BONDS * HID];
__device__ float g_gi  [N_BONDS * 3 * HID];
__device__ float g_msg [N_BONDS * HID];
__device__ float g_gh  [N_BONDS * 3 * HID];
__device__ float g_amsg[N_ATOMS * HID];

__device__ __nv_bfloat16 g_fb_hi [N_BONDS * KP_BOND];
__device__ __nv_bfloat16 g_fb_lo [N_BONDS * KP_BOND];
__device__ __nv_bfloat16 g_inp_hi[N_BONDS * KP_HID];
__device__ __nv_bfloat16 g_inp_lo[N_BONDS * KP_HID];
__device__ __nv_bfloat16 g_h_hi  [N_BONDS * KP_HID];
__device__ __nv_bfloat16 g_h_lo  [N_BONDS * KP_HID];
__device__ __nv_bfloat16 g_ain_hi[N_ATOMS * KP_CAT];
__device__ __nv_bfloat16 g_ain_lo[N_ATOMS * KP_CAT];
__device__ __nv_bfloat16 g_Wi_hi [HID * KP_BOND];
__device__ __nv_bfloat16 g_Wi_lo [HID * KP_BOND];
__device__ __nv_bfloat16 g_Wih_hi[3 * HID * KP_HID];
__device__ __nv_bfloat16 g_Wih_lo[3 * HID * KP_HID];
__device__ __nv_bfloat16 g_Whh_hi[3 * HID * KP_HID];
__device__ __nv_bfloat16 g_Whh_lo[3 * HID * KP_HID];
__device__ __nv_bfloat16 g_Wo_hi [HID * KP_CAT];
__device__ __nv_bfloat16 g_Wo_lo [HID * KP_CAT];

// ================= helpers ======================================================
__device__ __forceinline__ unsigned smem_u32(const void* p) {
    return (unsigned)__cvta_generic_to_shared(p);
}
__device__ __forceinline__ void cp16(unsigned dst, const void* src) {
    asm volatile("cp.async.cg.shared.global [%0], [%1], 16;\n" :: "r"(dst), "l"(src));
}
__device__ __forceinline__ void cp_commit() { asm volatile("cp.async.commit_group;\n"); }
__device__ __forceinline__ void cp_wait0()  { asm volatile("cp.async.wait_group 0;\n"); }
__device__ __forceinline__ void sts_zero16(unsigned dst) {
    asm volatile("st.shared.v4.b32 [%0], {%1,%1,%1,%1};" :: "r"(dst), "r"(0));
}
__device__ __forceinline__ void ldsm_x4(unsigned& r0, unsigned& r1, unsigned& r2,
                                        unsigned& r3, unsigned addr) {
    asm volatile("ldmatrix.sync.aligned.m8n8.x4.shared.b16 {%0,%1,%2,%3}, [%4];"
                 : "=r"(r0), "=r"(r1), "=r"(r2), "=r"(r3) : "r"(addr));
}
__device__ __forceinline__ void mma_bf16(float* c, const unsigned* a, const unsigned* b) {
    asm volatile(
        "mma.sync.aligned.m16n8k16.row.col.f32.bf16.bf16.f32 "
        "{%0,%1,%2,%3},{%4,%5,%6,%7},{%8,%9},{%0,%1,%2,%3};"
        : "+f"(c[0]), "+f"(c[1]), "+f"(c[2]), "+f"(c[3])
        : "r"(a[0]), "r"(a[1]), "r"(a[2]), "r"(a[3]), "r"(b[0]), "r"(b[1]));
}
__device__ __forceinline__ void bf16_split(float v, __nv_bfloat16& hi, __nv_bfloat16& lo) {
    hi = __float2bfloat16_rn(v);
    lo = __float2bfloat16_rn(v - __bfloat162float(hi));
}
__device__ __forceinline__ float sigmoidf1(float x) { return 1.f / (1.f + expf(-x)); }

// ================= bf16x3 TN GEMM (round-7 proven core) =========================
// C[m,n] = sum_k A[m,k]*B[n,k], A = Ah+Al, B = Bh+Bl (bf16 2-term splits).
// C += Al*Bh + Ah*Bl + Ah*Bh  (fp32 accumulate)
#define BM 128
#define BN 128
#define BK 32
#define ROWS 40                      // smem row stride in bf16 (32 + 8 pad)
#define BUF_ELEMS (2 * BM * ROWS)    // per buffer, 2 stages = 10240 bf16
#define SMEM_BYTES (4 * BUF_ELEMS * 2)  // 81920 B

__global__ void __launch_bounds__(256, 2)
mma_gemm_bf16x3(const __nv_bfloat16* __restrict__ Ahg, const __nv_bfloat16* __restrict__ Alg,
                const __nv_bfloat16* __restrict__ Bhg, const __nv_bfloat16* __restrict__ Blg,
                const float* __restrict__ bias, const float* __restrict__ mask,
                float* __restrict__ C, int M, int N, int KT, int KP, int relu)
{
    extern __shared__ __nv_bfloat16 smem[];
    __nv_bfloat16* Ah = smem;
    __nv_bfloat16* Al = smem + BUF_ELEMS;
    __nv_bfloat16* Bh = smem + 2 * BUF_ELEMS;
    __nv_bfloat16* Bl = smem + 3 * BUF_ELEMS;

    const int tid  = threadIdx.x;
    const int wid  = tid >> 5;
    const int lane = tid & 31;
    const int warp_m = wid & 1;     // 2 warps x 64 rows
    const int warp_n = wid >> 1;    // 4 warps x 32 cols
    const int m0 = blockIdx.y * BM;
    const int n0 = blockIdx.x * BN;
    const int mat = lane >> 3;      // ldmatrix address groups
    const int rw  = lane & 7;

    float acc[4][4][4];
    #pragma unroll
    for (int mi = 0; mi < 4; mi++)
        #pragma unroll
        for (int ni = 0; ni < 4; ni++)
            #pragma unroll
            for (int r = 0; r < 4; r++) acc[mi][ni][r] = 0.f;

    auto load_tile = [&](int kt, int s) {
        const int k0 = kt * BK;
        const int sb = s * BM * ROWS;
        #pragma unroll
        for (int i = 0; i < 2; i++) {
            int idx = tid + i * 256;
            int row = idx >> 2, seg = idx & 3;
            int kc = seg * 8;
            unsigned offA = smem_u32(&Ah[sb + row * ROWS + kc]);
            unsigned offAl = smem_u32(&Al[sb + row * ROWS + kc]);
            unsigned offB = smem_u32(&Bh[sb + row * ROWS + kc]);
            unsigned offBl = smem_u32(&Bl[sb + row * ROWS + kc]);
            int gm = m0 + row, gn = n0 + row;
            if (gm < M) {
                size_t go = (size_t)gm * KP + k0 + kc;
                cp16(offA, Ahg + go);
                cp16(offAl, Alg + go);
            } else { sts_zero16(offA); sts_zero16(offAl); }
            if (gn < N) {
                size_t go = (size_t)gn * KP + k0 + kc;
                cp16(offB, Bhg + go);
                cp16(offBl, Blg + go);
            } else { sts_zero16(offB); sts_zero16(offBl); }
        }
    };

    load_tile(0, 0);
    cp_commit();

    for (int kt = 0; kt < KT; kt++) {
        cp_wait0();
        __syncthreads();
        const int cur = kt & 1;
        if (kt + 1 < KT) load_tile(kt + 1, cur ^ 1);
        cp_commit();
        const int sb = cur * BM * ROWS;

        #pragma unroll
        for (int kk = 0; kk < BK; kk += 16) {
            unsigned ah[4][4], al[4][4];
            #pragma unroll
            for (int mi = 0; mi < 4; mi++) {
                int arow = warp_m * 64 + mi * 16 + ((mat & 1) << 3) + rw;
                int acol = kk + ((mat >> 1) << 3);
                unsigned ad = smem_u32(&Ah[sb + arow * ROWS + acol]);
                ldsm_x4(ah[mi][0], ah[mi][1], ah[mi][2], ah[mi][3], ad);
                unsigned ad2 = smem_u32(&Al[sb + arow * ROWS + acol]);
                ldsm_x4(al[mi][0], al[mi][1], al[mi][2], al[mi][3], ad2);
            }
            unsigned bh[4][2], bl[4][2];
            #pragma unroll
            for (int ni2 = 0; ni2 < 2; ni2++) {
                int brow = warp_n * 32 + ni2 * 16 + ((mat >> 1) << 3) + rw;
                int bcol = kk + ((mat & 1) << 3);
                unsigned r0, r1, r2, r3;
                unsigned bd = smem_u32(&Bh[sb + brow * ROWS + bcol]);
                ldsm_x4(r0, r1, r2, r3, bd);
                bh[ni2*2  ][0] = r0; bh[ni2*2  ][1] = r1;
                bh[ni2*2+1][0] = r2; bh[ni2*2+1][1] = r3;
                unsigned bd2 = smem_u32(&Bl[sb + brow * ROWS + bcol]);
                ldsm_x4(r0, r1, r2, r3, bd2);
                bl[ni2*2  ][0] = r0; bl[ni2*2  ][1] = r1;
                bl[ni2*2+1][0] = r2; bl[ni2*2+1][1] = r3;
            }
            #pragma unroll
            for (int mi = 0; mi < 4; mi++)
                #pragma unroll
                for (int ni = 0; ni < 4; ni++) {
                    mma_bf16(acc[mi][ni], al[mi], bh[ni]);   // lo*hi
                    mma_bf16(acc[mi][ni], ah[mi], bl[ni]);   // hi*lo
                    mma_bf16(acc[mi][ni], ah[mi], bh[ni]);   // hi*hi
                }
        }
        __syncthreads();
    }

    // epilogue
    const int g = lane >> 2, t = lane & 3;
    #pragma unroll
    for (int mi = 0; mi < 4; mi++) {
        #pragma unroll
        for (int ni = 0; ni < 4; ni++) {
            int cn = n0 + warp_n * 32 + ni * 8 + 2 * t;
            float b0 = 0.f, b1 = 0.f;
            if (bias) {
                if (cn     < N) b0 = bias[cn];
                if (cn + 1 < N) b1 = bias[cn + 1];
            }
            #pragma unroll
            for (int half = 0; half < 2; half++) {
                int rm = m0 + warp_m * 64 + mi * 16 + g + half * 8;
                if (rm >= M) continue;
                float v0 = acc[mi][ni][half * 2 + 0] + b0;
                float v1 = acc[mi][ni][half * 2 + 1] + b1;
                if (relu) { v0 = fmaxf(v0, 0.f); v1 = fmaxf(v1, 0.f); }
                if (mask) { float mk = mask[rm]; v0 *= mk; v1 *= mk; }
                if (cn + 1 < N) {
                    float2 v = {v0, v1};
                    *(float2*)(C + (size_t)rm * N + cn) = v;
                } else if (cn < N) {
                    C[(size_t)rm * N + cn] = v0;
                }
            }
        }
    }
}

// ================= split producers ==============================================
__global__ void split_bf16(const float* __restrict__ src,
                           __nv_bfloat16* __restrict__ hi,
                           __nv_bfloat16* __restrict__ lo,
                           int M, int K, int KP)
{
    int idx = blockIdx.x * blockDim.x + threadIdx.x;
    if (idx >= M * KP) return;
    int m = idx / KP;
    int k = idx - m * KP;
    float v = (k < K) ? src[(size_t)m * K + k] : 0.f;
    __nv_bfloat16 h, l;
    bf16_split(v, h, l);
    hi[idx] = h;
    lo[idx] = l;
}

// fused split of ALL weight matrices in one launch (range dispatch)
#define W1_END (HID * KP_BOND)                       // W_i
#define W2_END (W1_END + 3 * HID * KP_HID)           // W_ih
#define W3_END (W2_END + 3 * HID * KP_HID)           // W_hh
#define W4_END (W3_END + HID * KP_CAT)               // W_o
__global__ void split_weights_all(const float* __restrict__ W_i,
                                  const float* __restrict__ W_ih,
                                  const float* __restrict__ W_hh,
                                  const float* __restrict__ W_o,
                                  __nv_bfloat16* __restrict__ Wi_hi, __nv_bfloat16* __restrict__ Wi_lo,
                                  __nv_bfloat16* __restrict__ Wih_hi, __nv_bfloat16* __restrict__ Wih_lo,
                                  __nv_bfloat16* __restrict__ Whh_hi, __nv_bfloat16* __restrict__ Whh_lo,
                                  __nv_bfloat16* __restrict__ Wo_hi, __nv_bfloat16* __restrict__ Wo_lo)
{
    int idx = blockIdx.x * blockDim.x + threadIdx.x;
    if (idx >= W4_END) return;
    const float* src; __nv_bfloat16 *hi, *lo;
    int off, K, KP;
    if (idx < W1_END)      { src = W_i;  hi = Wi_hi;  lo = Wi_lo;  off = idx;          K = BOND_FDIM; KP = KP_BOND; }
    else if (idx < W2_END) { src = W_ih; hi = Wih_hi; lo = Wih_lo; off = idx - W1_END; K = HID;       KP = KP_HID; }
    else if (idx < W3_END) { src = W_hh; hi = Whh_hi; lo = Whh_lo; off = idx - W2_END; K = HID;       KP = KP_HID; }
    else                   { src = W_o;  hi = Wo_hi;  lo = Wo_lo;  off = idx - W3_END; K = CAT_DIM;   KP = KP_CAT; }
    int m = off / KP;
    int k = off - m * KP;
    float v = (k < K) ? src[(size_t)m * K + k] : 0.f;
    __nv_bfloat16 h, l;
    bf16_split(v, h, l);
    hi[off] = h;
    lo[off] = l;
}

__global__ void zero_pad_h(__nv_bfloat16* __restrict__ hi, __nv_bfloat16* __restrict__ lo)
{
    int idx = blockIdx.x * blockDim.x + threadIdx.x;
    const int PADW = KP_HID - HID;   // 20
    if (idx >= N_BONDS * PADW) return;
    int b = idx / PADW;
    int k = HID + (idx - b * PADW);
    hi[(size_t)b * KP_HID + k] = __float2bfloat16(0.f);
    lo[(size_t)b * KP_HID + k] = __float2bfloat16(0.f);
}

// ================= elementwise ==================================================
__global__ void gather_sum4(const float4* __restrict__ msg,
                            const int* __restrict__ a2b,
                            float4* __restrict__ amsg)
{
    int idx = blockIdx.x * blockDim.x + threadIdx.x;
    if (idx >= N_ATOMS * H4) return;
    int a = idx / H4;
    int j = idx - a * H4;
    const int* nb = a2b + (size_t)a * MAX_NB;
    float4 s = {0.f, 0.f, 0.f, 0.f};
    #pragma unroll
    for (int i = 0; i < MAX_NB; i++) {
        float4 v = msg[(size_t)nb[i] * H4 + j];
        s.x += v.x; s.y += v.y; s.z += v.z; s.w += v.w;
    }
    amsg[idx] = s;
}

// h = amsg[b2a] - msg[b2revb]; writes ONLY the bf16 hi/lo split (padded stride).
// The fp32 h is reconstructed downstream as hi+lo (exactly the operand the GEMM saw).
__global__ void hpre4_split(const float4* __restrict__ amsg,
                            const float4* __restrict__ msg,
                            const int* __restrict__ b2a,
                            const int* __restrict__ b2revb,
                            __nv_bfloat162* __restrict__ h_hi,
                            __nv_bfloat162* __restrict__ h_lo)
{
    int idx = blockIdx.x * blockDim.x + threadIdx.x;
    if (idx >= N_BONDS * H4) return;
    int b = idx / H4;
    int j = idx - b * H4;
    float4 u = amsg[(size_t)b2a[b] * H4 + j];
    float4 v = msg[(size_t)b2revb[b] * H4 + j];
    float4 o = {u.x - v.x, u.y - v.y, u.z - v.z, u.w - v.w};
    __nv_bfloat16 hx, lx, hy, ly, hz, lz, hw, lw;
    bf16_split(o.x, hx, lx);
    bf16_split(o.y, hy, ly);
    bf16_split(o.z, hz, lz);
    bf16_split(o.w, hw, lw);
    size_t base = (size_t)b * (KP_HID / 2) + j * 2;
    h_hi[base]     = __nv_bfloat162(hx, hy);
    h_hi[base + 1] = __nv_bfloat162(hz, hw);
    h_lo[base]     = __nv_bfloat162(lx, ly);
    h_lo[base + 1] = __nv_bfloat162(lz, lw);
}

__global__ void gru4(const float4* __restrict__ gi,
                     const float4* __restrict__ gh,
                     const __nv_bfloat162* __restrict__ h_hi,
                     const __nv_bfloat162* __restrict__ h_lo,
                     float4* __restrict__ out)
{
    int idx = blockIdx.x * blockDim.x + threadIdx.x;
    if (idx >= N_BONDS * H4) return;
    int b = idx / H4;
    int j = idx - b * H4;
    if (b == 0) { out[idx] = make_float4(0.f, 0.f, 0.f, 0.f); return; }
    size_t gb = (size_t)b * H34;
    float4 ir = gi[gb + j], iz = gi[gb + H4 + j], in4 = gi[gb + 2 * H4 + j];
    float4 hr = gh[gb + j], hz = gh[gb + H4 + j], hn4 = gh[gb + 2 * H4 + j];
    // reconstruct h = hi + lo
    size_t hb = (size_t)b * (KP_HID / 2) + j * 2;
    __nv_bfloat162 a0 = h_hi[hb], a1 = h_hi[hb + 1];
    __nv_bfloat162 c0 = h_lo[hb], c1 = h_lo[hb + 1];
    float4 hh;
    hh.x = __bfloat162float(a0.x) + __bfloat162float(c0.x);
    hh.y = __bfloat162float(a0.y) + __bfloat162float(c0.y);
    hh.z = __bfloat162float(a1.x) + __bfloat162float(c1.x);
    hh.w = __bfloat162float(a1.y) + __bfloat162float(c1.y);
    float4 o;
    {
        float r = sigmoidf1(ir.x + hr.x), z = sigmoidf1(iz.x + hz.x);
        float n = tanhf(in4.x + r * hn4.x);
        o.x = (1.f - z) * n + z * hh.x;
    }
    {
        float r = sigmoidf1(ir.y + hr.y), z = sigmoidf1(iz.y + hz.y);
        float n = tanhf(in4.y + r * hn4.y);
        o.y = (1.f - z) * n + z * hh.y;
    }
    {
        float r = sigmoidf1(ir.z + hr.z), z = sigmoidf1(iz.z + hz.z);
        float n = tanhf(in4.z + r * hn4.z);
        o.z = (1.f - z) * n + z * hh.z;
    }
    {
        float r = sigmoidf1(ir.w + hr.w), z = sigmoidf1(iz.w + hz.w);
        float n = tanhf(in4.w + r * hn4.w);
        o.w = (1.f - z) * n + z * hh.w;
    }
    out[idx] = o;
}

__global__ void concat_split(const float* __restrict__ f_atoms,
                             const float* __restrict__ amsg,
                             __nv_bfloat16* __restrict__ ain_hi,
                             __nv_bfloat16* __restrict__ ain_lo)
{
    int idx = blockIdx.x * blockDim.x + threadIdx.x;
    if (idx >= N_ATOMS * KP_CAT) return;
    int a = idx / KP_CAT;
    int k = idx - a * KP_CAT;
    float v = 0.f;
    if (k < ATOM_FDIM)      v = f_atoms[(size_t)a * ATOM_FDIM + k];
    else if (k < CAT_DIM)   v = amsg[(size_t)a * HID + (k - ATOM_FDIM)];
    __nv_bfloat16 h, l;
    bf16_split(v, h, l);
    ain_hi[idx] = h;
    ain_lo[idx] = l;
}

// ================= launch ========================================================
static inline dim3 gemm_grid(int M, int N) {
    return dim3((N + BN - 1) / BN, (M + BM - 1) / BM);
}

extern "C" void kernel_launch(void* const* d_in, const int* in_sizes, int n_in,
                              void* d_out, int out_size)
{
    const float* f_atoms = (const float*)d_in[0];
    const float* f_bonds = (const float*)d_in[1];
    const int*   a2b     = (const int*)  d_in[2];
    const int*   b2a     = (const int*)  d_in[3];
    const int*   b2revb  = (const int*)  d_in[4];
    const float* mask    = (const float*)d_in[8];
    const float* W_i     = (const float*)d_in[9];   // [300,147]
    const float* W_ih    = (const float*)d_in[10];  // [900,300]
    const float* W_hh    = (const float*)d_in[11];  // [900,300]
    const float* b_ih    = (const float*)d_in[12];
    const float* b_hh    = (const float*)d_in[13];
    const float* W_o_w   = (const float*)d_in[14];  // [300,433]
    const float* W_o_b   = (const float*)d_in[15];
    float* out = (float*)d_out;

    float *p_inp, *p_gi, *p_msg, *p_gh, *p_amsg;
    __nv_bfloat16 *p_fb_hi, *p_fb_lo, *p_inp_hi, *p_inp_lo, *p_h_hi, *p_h_lo;
    __nv_bfloat16 *p_ain_hi, *p_ain_lo;
    __nv_bfloat16 *p_Wi_hi, *p_Wi_lo, *p_Wih_hi, *p_Wih_lo, *p_Whh_hi, *p_Whh_lo;
    __nv_bfloat16 *p_Wo_hi, *p_Wo_lo;
    cudaGetSymbolAddress((void**)&p_inp,    g_inp);
    cudaGetSymbolAddress((void**)&p_gi,     g_gi);
    cudaGetSymbolAddress((void**)&p_msg,    g_msg);
    cudaGetSymbolAddress((void**)&p_gh,     g_gh);
    cudaGetSymbolAddress((void**)&p_amsg,   g_amsg);
    cudaGetSymbolAddress((void**)&p_fb_hi,  g_fb_hi);
    cudaGetSymbolAddress((void**)&p_fb_lo,  g_fb_lo);
    cudaGetSymbolAddress((void**)&p_inp_hi, g_inp_hi);
    cudaGetSymbolAddress((void**)&p_inp_lo, g_inp_lo);
    cudaGetSymbolAddress((void**)&p_h_hi,   g_h_hi);
    cudaGetSymbolAddress((void**)&p_h_lo,   g_h_lo);
    cudaGetSymbolAddress((void**)&p_ain_hi, g_ain_hi);
    cudaGetSymbolAddress((void**)&p_ain_lo, g_ain_lo);
    cudaGetSymbolAddress((void**)&p_Wi_hi,  g_Wi_hi);
    cudaGetSymbolAddress((void**)&p_Wi_lo,  g_Wi_lo);
    cudaGetSymbolAddress((void**)&p_Wih_hi, g_Wih_hi);
    cudaGetSymbolAddress((void**)&p_Wih_lo, g_Wih_lo);
    cudaGetSymbolAddress((void**)&p_Whh_hi, g_Whh_hi);
    cudaGetSymbolAddress((void**)&p_Whh_lo, g_Whh_lo);
    cudaGetSymbolAddress((void**)&p_Wo_hi,  g_Wo_hi);
    cudaGetSymbolAddress((void**)&p_Wo_lo,  g_Wo_lo);

    static bool attr_set = false;
    if (!attr_set) {
        cudaFuncSetAttribute(mma_gemm_bf16x3,
                             cudaFuncAttributeMaxDynamicSharedMemorySize, SMEM_BYTES);
        attr_set = true;
    }

    const int EW = 256;
    int nb4_grid = (N_BONDS * H4 + EW - 1) / EW;
    int na4_grid = (N_ATOMS * H4 + EW - 1) / EW;
    auto sgrid = [](long n) { return (int)((n + 255) / 256); };

    // Launch order arranged so ncu's "-s 5 -c 1" captures launch #6 = the gi GEMM
    // (same shape as the dominant gh GEMMs).
    // 1. split f_bonds
    split_bf16<<<sgrid((long)N_BONDS * KP_BOND), 256>>>(f_bonds, p_fb_hi, p_fb_lo,
                                                        N_BONDS, BOND_FDIM, KP_BOND);
    // 2. split all weights (one fused launch)
    split_weights_all<<<sgrid((long)W4_END), 256>>>(
        W_i, W_ih, W_hh, W_o_w,
        p_Wi_hi, p_Wi_lo, p_Wih_hi, p_Wih_lo,
        p_Whh_hi, p_Whh_lo, p_Wo_hi, p_Wo_lo);
    // 3. zero h pad columns
    zero_pad_h<<<sgrid((long)N_BONDS * (KP_HID - HID)), 256>>>(p_h_hi, p_h_lo);

    // 4. inp = f_bonds @ W_i^T         [90000,300] KP=160 (KT=5)
    mma_gemm_bf16x3<<<gemm_grid(N_BONDS, HID), 256, SMEM_BYTES>>>(
        p_fb_hi, p_fb_lo, p_Wi_hi, p_Wi_lo, nullptr, nullptr,
        p_inp, N_BONDS, HID, KP_BOND / BK, KP_BOND, 0);

    // 5. split inp
    split_bf16<<<sgrid((long)N_BONDS * KP_HID), 256>>>(p_inp, p_inp_hi, p_inp_lo,
                                                       N_BONDS, HID, KP_HID);

    // 6. gi = inp @ W_ih^T + b_ih      [90000,900] KP=320 (KT=10)  <- ncu target
    mma_gemm_bf16x3<<<gemm_grid(N_BONDS, 3 * HID), 256, SMEM_BYTES>>>(
        p_inp_hi, p_inp_lo, p_Wih_hi, p_Wih_lo, b_ih, nullptr,
        p_gi, N_BONDS, 3 * HID, KP_HID / BK, KP_HID, 0);

    const float* msg_src = p_inp;
    for (int it = 0; it < DEPTH - 1; it++) {
        gather_sum4<<<na4_grid, EW>>>((const float4*)msg_src, a2b, (float4*)p_amsg);
        hpre4_split<<<nb4_grid, EW>>>((const float4*)p_amsg, (const float4*)msg_src,
                                      b2a, b2revb,
                                      (__nv_bfloat162*)p_h_hi, (__nv_bfloat162*)p_h_lo);
        // gh = h @ W_hh^T + b_hh       [90000,900] K=300
        mma_gemm_bf16x3<<<gemm_grid(N_BONDS, 3 * HID), 256, SMEM_BYTES>>>(
            p_h_hi, p_h_lo, p_Whh_hi, p_Whh_lo, b_hh, nullptr,
            p_gh, N_BONDS, 3 * HID, KP_HID / BK, KP_HID, 0);
        gru4<<<nb4_grid, EW>>>((const float4*)p_gi, (const float4*)p_gh,
                               (const __nv_bfloat162*)p_h_hi,
                               (const __nv_bfloat162*)p_h_lo, (float4*)p_msg);
        msg_src = p_msg;
    }

    gather_sum4<<<na4_grid, EW>>>((const float4*)msg_src, a2b, (float4*)p_amsg);
    concat_split<<<sgrid((long)N_ATOMS * KP_CAT), 256>>>(f_atoms, p_amsg,
                                                         p_ain_hi, p_ain_lo);
    // out = relu(ain @ W_o_w^T + W_o_b) * mask   [40000,300] KP=448 (KT=14)
    mma_gemm_bf16x3<<<gemm_grid(N_ATOMS, HID), 256, SMEM_BYTES>>>(
        p_ain_hi, p_ain_lo, p_Wo_hi, p_Wo_lo, W_o_b, mask,
        out, N_ATOMS, HID, KP_CAT / BK, KP_CAT, 1);
}